// round 5
// baseline (speedup 1.0000x reference)
#include <cuda_runtime.h>
#include <cstdint>

// Problem shape (fixed by setup_inputs): 3 tensors of [B=8, C=256, H=64, W=64] fp32.
#define NB 8
#define NC 256
#define HW 4096              // 64*64
#define K_SEL 2048           // top 50%
#define PER_BATCH (NC * HW)  // 1,048,576 = 2^20 elements
#define PER_TENSOR (NB * PER_BATCH)  // 8,388,608 = 2^23
#define NPOS (3 * NB * HW)   // 98,304 (t,b,hw) positions

// Scratch (allocation-free rule: __device__ globals)
__device__ float g_imp[NPOS];    // per-position importance (raw sum of |x| over C)
__device__ float g_mask[NPOS];   // 1.0f / 0.0f mask

// ---------------------------------------------------------------------------
// Kernel 1: importance = sequential fp32 sum over C of |x|  (order matters:
// aiming to match the reference's over-C accumulation as closely as possible).
// ---------------------------------------------------------------------------
__global__ void imp_kernel(const float* __restrict__ in0,
                           const float* __restrict__ in1,
                           const float* __restrict__ in2) {
    int p = blockIdx.x * blockDim.x + threadIdx.x;
    if (p >= NPOS) return;
    int tb = p >> 12;          // t*8 + b
    int hw = p & (HW - 1);
    int t  = tb >> 3;
    int b  = tb & 7;
    const float* src = (t == 0) ? in0 : (t == 1) ? in1 : in2;
    const float* base = src + ((size_t)b << 20) + hw;

    float s = 0.0f;
    #pragma unroll
    for (int c = 0; c < NC; c += 8) {
        float v0 = fabsf(base[(size_t)(c + 0) << 12]);
        float v1 = fabsf(base[(size_t)(c + 1) << 12]);
        float v2 = fabsf(base[(size_t)(c + 2) << 12]);
        float v3 = fabsf(base[(size_t)(c + 3) << 12]);
        float v4 = fabsf(base[(size_t)(c + 4) << 12]);
        float v5 = fabsf(base[(size_t)(c + 5) << 12]);
        float v6 = fabsf(base[(size_t)(c + 6) << 12]);
        float v7 = fabsf(base[(size_t)(c + 7) << 12]);
        // strictly sequential adds (no reassociation)
        s += v0; s += v1; s += v2; s += v3;
        s += v4; s += v5; s += v6; s += v7;
    }
    g_imp[p] = s;
}

// ---------------------------------------------------------------------------
// Kernel 2: per (t,b) exact k-th-largest selection via MSB-first radix select
// on composite keys (imp_bits << 12) | (4095 - hw). Keys are unique, so
// key >= threshold selects exactly K_SEL positions with top_k tie semantics
// (lowest index wins ties). One block per (t,b); 24 blocks total.
// ---------------------------------------------------------------------------
__global__ void select_kernel() {
    __shared__ unsigned long long sk[HW];       // 32 KB
    __shared__ unsigned int hist[256];
    __shared__ unsigned long long s_pref;
    __shared__ unsigned int s_k;

    const int tb = blockIdx.x;                  // 0..23
    const int base = tb * HW;
    const int tid = threadIdx.x;
    const int bd = blockDim.x;

    for (int i = tid; i < HW; i += bd) {
        // imp >= 0 always -> float bits preserve order as unsigned
        unsigned int fb = __float_as_uint(g_imp[base + i]);
        sk[i] = ((unsigned long long)fb << 12) | (unsigned long long)(HW - 1 - i);
    }
    if (tid == 0) { s_pref = 0ull; s_k = K_SEL; }
    __syncthreads();

    #pragma unroll
    for (int shift = 40; shift >= 0; shift -= 8) {
        for (int i = tid; i < 256; i += bd) hist[i] = 0u;
        __syncthreads();
        unsigned long long pref = s_pref;
        for (int i = tid; i < HW; i += bd) {
            unsigned long long key = sk[i];
            if ((key >> (shift + 8)) == pref)
                atomicAdd(&hist[(unsigned)((key >> shift) & 255ull)], 1u);
        }
        __syncthreads();
        if (tid == 0) {
            unsigned int k = s_k;
            int d = 255;
            for (;; d--) {
                unsigned int c = hist[d];
                if (c >= k) break;
                k -= c;
            }
            s_k = k;
            s_pref = (pref << 8) | (unsigned long long)d;
        }
        __syncthreads();
    }

    const unsigned long long thresh = s_pref;   // the K_SEL-th largest key
    for (int i = tid; i < HW; i += bd)
        g_mask[base + i] = (sk[i] >= thresh) ? 1.0f : 0.0f;
}

// ---------------------------------------------------------------------------
// Kernel 3: out = in * mask, float4 vectorized. Mask (384 KB) stays in L2.
// Output layout: tensor0 | tensor1 | tensor2 concatenated.
// ---------------------------------------------------------------------------
__global__ void mask_kernel(const float* __restrict__ in0,
                            const float* __restrict__ in1,
                            const float* __restrict__ in2,
                            float* __restrict__ out) {
    long long i = (long long)blockIdx.x * blockDim.x + threadIdx.x;  // float4 index
    long long e = i << 2;                                            // element index
    if (e >= (long long)3 * PER_TENSOR) return;
    int t = (int)(e >> 23);
    int r = (int)(e & (PER_TENSOR - 1));
    const float* src = (t == 0) ? in0 : (t == 1) ? in1 : in2;
    // mask index: (t*8 + b)*4096 + hw
    int midx = (t << 15) + ((r >> 20) << 12) + (r & (HW - 1));

    float4 x = *reinterpret_cast<const float4*>(src + r);
    float4 m = *reinterpret_cast<const float4*>(&g_mask[midx]);
    float4 y;
    y.x = x.x * m.x;
    y.y = x.y * m.y;
    y.z = x.z * m.z;
    y.w = x.w * m.w;
    reinterpret_cast<float4*>(out)[i] = y;
}

// ---------------------------------------------------------------------------
extern "C" void kernel_launch(void* const* d_in, const int* in_sizes, int n_in,
                              void* d_out, int out_size) {
    const float* a = (const float*)d_in[0];
    const float* b = (const float*)d_in[1];
    const float* c = (const float*)d_in[2];
    float* out = (float*)d_out;

    // 1) importance
    imp_kernel<<<(NPOS + 255) / 256, 256>>>(a, b, c);
    // 2) exact top-k thresholds + mask build (24 blocks)
    select_kernel<<<3 * NB, 256>>>();
    // 3) masked write
    long long n4 = (long long)3 * PER_TENSOR / 4;   // 6,291,456
    mask_kernel<<<(unsigned)((n4 + 255) / 256), 256>>>(a, b, c, out);
}

// round 9
// speedup vs baseline: 1.4190x; 1.4190x over previous
#include <cuda_runtime.h>
#include <cstdint>

// Problem shape (fixed by setup_inputs): 3 tensors of [B=8, C=256, H=64, W=64] fp32.
#define NB 8
#define NC 256
#define HW 4096              // 64*64
#define K_SEL 2048           // top 50%
#define PER_BATCH (NC * HW)  // 1,048,576 = 2^20 elements
#define PER_TENSOR (NB * PER_BATCH)  // 8,388,608 = 2^23
#define NPOS (3 * NB * HW)   // 98,304 (t,b,hw) positions
#define NTB 24               // 3 * NB

// Scratch (allocation-free rule: __device__ globals)
__device__ float        g_imp[NPOS];           // per-position importance (sum |x| over C)
__device__ unsigned int g_maskbits[NTB * 128]; // 4096-bit mask per (t,b): 12 KB total

// ---------------------------------------------------------------------------
// Kernel 1: importance = strictly-sequential fp32 sum over C of |x|.
// Order of the adds must stay ascending-c and non-reassociated (rel_err=0.0
// confirmed with this order). Unroll 16 only batches the LOADS (MLP 8->16);
// the adds remain a single sequential chain.
// ---------------------------------------------------------------------------
__global__ void imp_kernel(const float* __restrict__ in0,
                           const float* __restrict__ in1,
                           const float* __restrict__ in2) {
    int p = blockIdx.x * blockDim.x + threadIdx.x;
    if (p >= NPOS) return;
    int tb = p >> 12;          // t*8 + b
    int hw = p & (HW - 1);
    int t  = tb >> 3;
    int b  = tb & 7;
    const float* src = (t == 0) ? in0 : (t == 1) ? in1 : in2;
    const float* base = src + ((size_t)b << 20) + hw;

    float s = 0.0f;
    #pragma unroll
    for (int c = 0; c < NC; c += 16) {
        float v[16];
        #pragma unroll
        for (int j = 0; j < 16; j++)
            v[j] = fabsf(base[(size_t)(c + j) << 12]);
        #pragma unroll
        for (int j = 0; j < 16; j++)
            s += v[j];          // strictly sequential, ascending c
    }
    g_imp[p] = s;
}

// ---------------------------------------------------------------------------
// Kernel 2: per (t,b) exact k-th-largest via MSB-first radix select on
// composite keys (imp_bits << 12) | (4095 - hw). Keys unique => exactly
// K_SEL selected, top_k lowest-index tie semantics.
// Contention fix: importance values concentrate (same exponent byte), so use
// warp-aggregated atomics (__match_any) — 1 atomic per distinct digit per
// warp instead of 32-way same-address serialization. Digit selection is a
// warp-0 scan instead of a serial 256-entry loop.
// One block of 512 threads per (t,b); 24 blocks.
// ---------------------------------------------------------------------------
__global__ void select_kernel() {
    __shared__ unsigned long long sk[HW];       // 32 KB
    __shared__ unsigned int hist[256];
    __shared__ unsigned long long s_pref;
    __shared__ unsigned int s_k;

    const int tb   = blockIdx.x;                // 0..23
    const int base = tb * HW;
    const int tid  = threadIdx.x;
    const int bd   = blockDim.x;                // 512
    const int lane = tid & 31;

    for (int i = tid; i < HW; i += bd) {
        // imp >= 0 always -> float bits preserve order as unsigned
        unsigned int fb = __float_as_uint(g_imp[base + i]);
        sk[i] = ((unsigned long long)fb << 12) | (unsigned long long)(HW - 1 - i);
    }
    if (tid == 0) { s_pref = 0ull; s_k = K_SEL; }
    __syncthreads();

    #pragma unroll
    for (int shift = 40; shift >= 0; shift -= 8) {
        if (tid < 256) hist[tid] = 0u;
        __syncthreads();
        const unsigned long long pref = s_pref;
        const unsigned int k = s_k;

        // histogram with warp-aggregated atomics
        for (int i = tid; i < HW; i += bd) {
            unsigned long long key = sk[i];
            bool pred = ((key >> (shift + 8)) == pref);
            unsigned pmask = __ballot_sync(0xffffffffu, pred);
            if (pred) {
                unsigned d = (unsigned)((key >> shift) & 255ull);
                unsigned grp = __match_any_sync(pmask, d);
                if (lane == (__ffs(grp) - 1))
                    atomicAdd(&hist[d], __popc(grp));
            }
        }
        __syncthreads();

        // warp 0: find digit d (from 255 down) where cumulative count reaches k
        if (tid < 32) {
            int base_d = 255 - tid * 8;         // lane covers [base_d-7 .. base_d]
            unsigned sum8 = 0;
            #pragma unroll
            for (int j = 0; j < 8; j++) sum8 += hist[base_d - j];
            // inclusive scan from lane 0 (topmost digits) downward
            unsigned pre = sum8;
            #pragma unroll
            for (int off = 1; off < 32; off <<= 1) {
                unsigned v = __shfl_up_sync(0xffffffffu, pre, off);
                if (tid >= off) pre += v;
            }
            unsigned before = pre - sum8;       // count of keys in higher digit groups
            if (before < k && k <= pre) {       // exactly one lane satisfies this
                unsigned rem = k - before;
                for (int d = base_d; ; d--) {
                    unsigned c = hist[d];
                    if (c >= rem) { s_k = rem; s_pref = (pref << 8) | (unsigned)d; break; }
                    rem -= c;
                }
            }
        }
        __syncthreads();
    }

    const unsigned long long thresh = s_pref;   // the K_SEL-th largest key
    // emit bitmask: bit (i&31) of word i>>5 = selected(i)
    for (int i = tid; i < HW; i += bd) {
        bool sel = (sk[i] >= thresh);
        unsigned bal = __ballot_sync(0xffffffffu, sel);
        if (lane == 0) g_maskbits[tb * 128 + (i >> 5)] = bal;
    }
}

// ---------------------------------------------------------------------------
// Kernel 3: out = in * mask, float4 vectorized, bitmask (12 KB, L1/L2-hot).
// Output layout: tensor0 | tensor1 | tensor2 concatenated.
// ---------------------------------------------------------------------------
__global__ void mask_kernel(const float* __restrict__ in0,
                            const float* __restrict__ in1,
                            const float* __restrict__ in2,
                            float* __restrict__ out) {
    long long i = (long long)blockIdx.x * blockDim.x + threadIdx.x;  // float4 index
    long long e = i << 2;                                            // element index
    if (e >= (long long)3 * PER_TENSOR) return;
    int t = (int)(e >> 23);
    int r = (int)(e & (PER_TENSOR - 1));
    const float* src = (t == 0) ? in0 : (t == 1) ? in1 : in2;
    int b  = r >> 20;
    int hw = r & (HW - 1);                     // multiple of 4

    unsigned w = __ldg(&g_maskbits[((t << 3) + b) * 128 + (hw >> 5)]);
    unsigned mb = (w >> (hw & 31)) & 0xFu;     // 4 mask bits for these elements

    float4 x = *reinterpret_cast<const float4*>(src + r);
    // multiply (not select) to reproduce reference's fm*0.0 sign semantics
    float4 y;
    y.x = x.x * ((mb & 1u) ? 1.0f : 0.0f);
    y.y = x.y * ((mb & 2u) ? 1.0f : 0.0f);
    y.z = x.z * ((mb & 4u) ? 1.0f : 0.0f);
    y.w = x.w * ((mb & 8u) ? 1.0f : 0.0f);
    reinterpret_cast<float4*>(out)[i] = y;
}

// ---------------------------------------------------------------------------
extern "C" void kernel_launch(void* const* d_in, const int* in_sizes, int n_in,
                              void* d_out, int out_size) {
    const float* a = (const float*)d_in[0];
    const float* b = (const float*)d_in[1];
    const float* c = (const float*)d_in[2];
    float* out = (float*)d_out;

    // 1) importance
    imp_kernel<<<(NPOS + 255) / 256, 256>>>(a, b, c);
    // 2) exact top-k + bitmask build (24 blocks x 512 threads)
    select_kernel<<<NTB, 512>>>();
    // 3) masked write
    long long n4 = (long long)3 * PER_TENSOR / 4;   // 6,291,456
    mask_kernel<<<(unsigned)((n4 + 255) / 256), 256>>>(a, b, c, out);
}